// round 1
// baseline (speedup 1.0000x reference)
#include <cuda_runtime.h>

#define BB 4
#define SS 4096
#define HH 1024
#define DD 64
#define NEG_INF_F (-1.0e12f)

// Scratch for K, Q, V projections: 3 x [B*S, D] fp32 = 12 MB
__device__ float g_KQV[3][BB * SS * DD];

// ---------------------------------------------------------------------------
// Fused projection: for each row m of x [16384 x 1024], compute
//   K[m] = x[m] @ Wk^T, Q[m] = x[m] @ Wq^T, V[m] = x[m] @ Wv^T
// BM=64 rows, BN=192 (all three outputs), BK=16. 256 threads, 4x12 microtile.
// ---------------------------------------------------------------------------
__global__ void proj_kernel(const float* __restrict__ x,
                            const float* __restrict__ Wk,
                            const float* __restrict__ Wq,
                            const float* __restrict__ Wv) {
    __shared__ float Xs[64][17];
    __shared__ float Ws[192][17];

    const int tid = threadIdx.x;
    const int ty = tid >> 4;          // 0..15 -> 4 rows each
    const int tx = tid & 15;          // 0..15 -> 12 cols each (strided by 16)
    const int m0 = blockIdx.x * 64;

    float acc[4][12];
#pragma unroll
    for (int i = 0; i < 4; i++)
#pragma unroll
        for (int j = 0; j < 12; j++) acc[i][j] = 0.0f;

    for (int k0 = 0; k0 < HH; k0 += 16) {
        // Load Xs: 64x16 = 1024 elems, 4 per thread
#pragma unroll
        for (int i = 0; i < 4; i++) {
            int idx = tid + i * 256;
            int r = idx >> 4, c = idx & 15;
            Xs[r][c] = x[(size_t)(m0 + r) * HH + k0 + c];
        }
        // Load Ws: 192x16 = 3072 elems, 12 per thread. Rows 0..63 = Wk,
        // 64..127 = Wq, 128..191 = Wv.
#pragma unroll
        for (int i = 0; i < 12; i++) {
            int idx = tid + i * 256;
            int r = idx >> 4, c = idx & 15;
            const float* W = (r < 64) ? Wk : ((r < 128) ? Wq : Wv);
            int rr = r & 63;
            Ws[r][c] = W[(size_t)rr * HH + k0 + c];
        }
        __syncthreads();

#pragma unroll
        for (int kk = 0; kk < 16; kk++) {
            float a[4], b[12];
#pragma unroll
            for (int i = 0; i < 4; i++) a[i] = Xs[ty * 4 + i][kk];
#pragma unroll
            for (int j = 0; j < 12; j++) b[j] = Ws[tx + 16 * j][kk];
#pragma unroll
            for (int i = 0; i < 4; i++)
#pragma unroll
                for (int j = 0; j < 12; j++) acc[i][j] += a[i] * b[j];
        }
        __syncthreads();
    }

#pragma unroll
    for (int j = 0; j < 12; j++) {
        int n = tx + 16 * j;          // 0..191
        float* out = g_KQV[n >> 6];
        int d = n & 63;
#pragma unroll
        for (int i = 0; i < 4; i++)
            out[(size_t)(m0 + 4 * ty + i) * DD + d] = acc[i][j];
    }
}

// ---------------------------------------------------------------------------
// Flash-style attention with swapped roles:
//   out[b,s,:] = softmax_t( scale * K[b,s]·Q[b,t] , mask on t ) @ V[b,t,:]
// Block: 64 K-rows, loop over t in blocks of 64. 256 threads.
// Phase 1 thread map: rows 4*ty+i, cols tx+16*j (conflict-friendly).
// Phase 2 thread map: rows 4*ty+i, d-cols 4*tx+j (float4 V loads).
// Shared stride 68 floats: 16B-aligned rows, 2-way-max bank conflicts.
// ---------------------------------------------------------------------------
#define LDS 68

__global__ void attn_kernel(const int* __restrict__ mask,
                            float* __restrict__ out) {
    extern __shared__ float sm[];
    float* Ks = sm;                    // 64 * LDS
    float* Qs = Ks + 64 * LDS;
    float* Vs = Qs + 64 * LDS;
    float* Ps = Vs + 64 * LDS;
    int* ms = (int*)(Ps + 64 * LDS);   // 64 ints

    const int b = blockIdx.y;
    const int r0 = blockIdx.x * 64;
    const float* K = g_KQV[0] + (size_t)b * SS * DD;
    const float* Q = g_KQV[1] + (size_t)b * SS * DD;
    const float* V = g_KQV[2] + (size_t)b * SS * DD;

    const int tid = threadIdx.x;
    const int ty = tid >> 4;
    const int tx = tid & 15;
    const float scale = 0.125f;        // 1/sqrt(64)

    // Load K block once
    for (int i = tid; i < 64 * 64; i += 256) {
        int r = i >> 6, c = i & 63;
        Ks[r * LDS + c] = K[(size_t)(r0 + r) * DD + c];
    }

    float m_i[4], l_i[4], O[4][4];
#pragma unroll
    for (int i = 0; i < 4; i++) {
        m_i[i] = -1e30f;
        l_i[i] = 0.0f;
#pragma unroll
        for (int j = 0; j < 4; j++) O[i][j] = 0.0f;
    }

    for (int t0 = 0; t0 < SS; t0 += 64) {
        __syncthreads();               // prev phase-2 done (and Ks load on iter 0)
        for (int i = tid; i < 64 * 64; i += 256) {
            int r = i >> 6, c = i & 63;
            Qs[r * LDS + c] = Q[(size_t)(t0 + r) * DD + c];
            Vs[r * LDS + c] = V[(size_t)(t0 + r) * DD + c];
        }
        if (tid < 64) ms[tid] = mask[b * SS + t0 + tid];
        __syncthreads();

        // Phase 1: sv[i][j] = K[r0+4ty+i] . Q[t0 + tx+16j]
        float sv[4][4];
#pragma unroll
        for (int i = 0; i < 4; i++)
#pragma unroll
            for (int j = 0; j < 4; j++) sv[i][j] = 0.0f;

#pragma unroll
        for (int d = 0; d < 64; d++) {
            float a[4], q[4];
#pragma unroll
            for (int i = 0; i < 4; i++) a[i] = Ks[(4 * ty + i) * LDS + d];
#pragma unroll
            for (int j = 0; j < 4; j++) q[j] = Qs[(tx + 16 * j) * LDS + d];
#pragma unroll
            for (int i = 0; i < 4; i++)
#pragma unroll
                for (int j = 0; j < 4; j++) sv[i][j] += a[i] * q[j];
        }

        // scale + column mask
#pragma unroll
        for (int j = 0; j < 4; j++) {
            bool masked = (ms[tx + 16 * j] == 0);
#pragma unroll
            for (int i = 0; i < 4; i++)
                sv[i][j] = masked ? NEG_INF_F : sv[i][j] * scale;
        }

        // Online softmax per row (16-lane reductions; lanes with same ty are
        // 16 contiguous lanes of the warp, so xor-shfl 1..8 stays in-group).
#pragma unroll
        for (int i = 0; i < 4; i++) {
            float rm = fmaxf(fmaxf(sv[i][0], sv[i][1]),
                             fmaxf(sv[i][2], sv[i][3]));
#pragma unroll
            for (int off = 1; off < 16; off <<= 1)
                rm = fmaxf(rm, __shfl_xor_sync(0xffffffffu, rm, off));
            float mn = fmaxf(m_i[i], rm);
            float alpha = __expf(m_i[i] - mn);
            m_i[i] = mn;
            float rs = 0.0f;
#pragma unroll
            for (int j = 0; j < 4; j++) {
                float p = __expf(sv[i][j] - mn);
                sv[i][j] = p;
                rs += p;
            }
#pragma unroll
            for (int off = 1; off < 16; off <<= 1)
                rs += __shfl_xor_sync(0xffffffffu, rs, off);
            l_i[i] = l_i[i] * alpha + rs;
#pragma unroll
            for (int j = 0; j < 4; j++) O[i][j] *= alpha;
        }

        // Stage P into smem (consecutive tx -> conflict-free)
#pragma unroll
        for (int i = 0; i < 4; i++)
#pragma unroll
            for (int j = 0; j < 4; j++)
                Ps[(4 * ty + i) * LDS + tx + 16 * j] = sv[i][j];
        __syncthreads();

        // Phase 2: O[i][4tx+j] += sum_c Ps[4ty+i][c] * Vs[c][4tx+j]
#pragma unroll
        for (int c = 0; c < 64; c++) {
            float p[4];
#pragma unroll
            for (int i = 0; i < 4; i++) p[i] = Ps[(4 * ty + i) * LDS + c];
            float4 v = *(const float4*)&Vs[c * LDS + 4 * tx];
#pragma unroll
            for (int i = 0; i < 4; i++) {
                O[i][0] += p[i] * v.x;
                O[i][1] += p[i] * v.y;
                O[i][2] += p[i] * v.z;
                O[i][3] += p[i] * v.w;
            }
        }
    }

    // Epilogue: normalize and store
#pragma unroll
    for (int i = 0; i < 4; i++) {
        float inv = 1.0f / l_i[i];
        int r = r0 + 4 * ty + i;
        float4 o4 = make_float4(O[i][0] * inv, O[i][1] * inv,
                                O[i][2] * inv, O[i][3] * inv);
        *(float4*)&out[((size_t)b * SS + r) * DD + 4 * tx] = o4;
    }
}

extern "C" void kernel_launch(void* const* d_in, const int* in_sizes, int n_in,
                              void* d_out, int out_size) {
    const float* x    = (const float*)d_in[0];
    const int*   mask = (const int*)d_in[1];
    const float* Wk   = (const float*)d_in[2];
    const float* Wq   = (const float*)d_in[3];
    const float* Wv   = (const float*)d_in[4];
    float* out = (float*)d_out;

    // Projections: 16384 rows / 64 per block
    proj_kernel<<<256, 256>>>(x, Wk, Wq, Wv);

    // Attention: 64 row-blocks x 4 batches
    const int smem_bytes = 4 * 64 * LDS * (int)sizeof(float) + 64 * (int)sizeof(int);
    cudaFuncSetAttribute(attn_kernel,
                         cudaFuncAttributeMaxDynamicSharedMemorySize, smem_bytes);
    dim3 grid(64, 4);
    attn_kernel<<<grid, 256, smem_bytes>>>(mask, out);
}